// round 9
// baseline (speedup 1.0000x reference)
#include <cuda_runtime.h>

#define D       64
#define DV      16          // D/4 float4 per row
#define MAX_N   100000
#define MAX_E   1700000
#define NB      128         // persistent grid: <= SM count -> all resident
#define TB      1024

// ---------------------------------------------------------------------------
// Device-global scratch (no allocation allowed).
// g_cnt is zero at load and restored to zero each execution (read-and-clear).
// Barrier gen/cnt are self-restoring across graph replays.
// ---------------------------------------------------------------------------
__device__ int    g_cnt[MAX_N];        // histogram of destination rows
__device__ int    g_off[MAX_N + 1];    // exclusive CSR offsets
__device__ int    g_pos[MAX_N];        // working cursor for binning
__device__ int    g_bsum[NB];          // per-chunk scan totals
__device__ int2   g_edge[MAX_E];       // binned (col, val-bits) pairs
__device__ float4 g_Y[MAX_N * DV];     // Y = X @ W^T

__device__ volatile unsigned g_bar_gen;
__device__ unsigned          g_bar_cnt;

// Sense-reversing software grid barrier. Safe because grid (NB=128) is fully
// resident in wave 1 (128 <= SM count, 1024 thr/block, regs capped).
__device__ __forceinline__ void grid_barrier() {
    __syncthreads();
    if (threadIdx.x == 0) {
        unsigned gen = g_bar_gen;
        __threadfence();
        unsigned my = atomicAdd(&g_bar_cnt, 1u);
        if (my == gridDim.x - 1) {
            g_bar_cnt = 0;
            __threadfence();
            g_bar_gen = gen + 1;
        } else {
            while (g_bar_gen == gen) { }
            __threadfence();
        }
    }
    __syncthreads();
}

// ---------------------------------------------------------------------------
// Fused CSR build: hist -> chunk scan -> prefix apply -> bin, one kernel.
// __launch_bounds__(TB, 2) caps regs at 32/thread so the concurrent GEMM's
// blocks can co-reside on the same SMs.
// ---------------------------------------------------------------------------
__global__ __launch_bounds__(TB, 2) void csr_build_kernel(
    const int* __restrict__ row, const int* __restrict__ col,
    const float* __restrict__ vals, int E, int N)
{
    const int tid    = threadIdx.x;
    const int bid    = blockIdx.x;
    const int gtid   = bid * TB + tid;
    const int stride = NB * TB;            // 131072
    const int nch    = (N + TB - 1) / TB;  // 98 chunks of 1024

    // ---- Phase 1: histogram of row[] --------------------------------------
    for (int e = gtid; e < E; e += stride)
        atomicAdd(&g_cnt[__ldg(row + e)], 1);

    grid_barrier();

    // ---- Phase 2: per-chunk exclusive scan (block b scans chunk b) --------
    __shared__ int wsum[32];
    if (bid < nch) {
        int i = bid * TB + tid;
        int v = 0;
        if (i < N) { v = g_cnt[i]; g_cnt[i] = 0; }   // read + restore invariant

        int lane = tid & 31;
        int wid  = tid >> 5;

        int s = v;
#pragma unroll
        for (int d = 1; d < 32; d <<= 1) {
            int t = __shfl_up_sync(0xFFFFFFFFu, s, d);
            if (lane >= d) s += t;
        }
        if (lane == 31) wsum[wid] = s;
        __syncthreads();
        if (wid == 0) {
            int ws = wsum[lane];
#pragma unroll
            for (int d = 1; d < 32; d <<= 1) {
                int t = __shfl_up_sync(0xFFFFFFFFu, ws, d);
                if (lane >= d) ws += t;
            }
            wsum[lane] = ws;
        }
        __syncthreads();
        int incl = s + (wid == 0 ? 0 : wsum[wid - 1]);
        if (i < N) g_off[i] = incl - v;                 // chunk-local exclusive
        if (tid == TB - 1) g_bsum[bid] = incl;          // chunk total
    }

    grid_barrier();

    // ---- Phase 3: add chunk prefix (redundant reduce over <=127 totals),
    //               write final g_off and init g_pos -----------------------
    __shared__ int s_part[4];
    __shared__ int s_pref;
    if (bid < nch) {
        if (tid < 128) {
            int vp = (tid < bid) ? g_bsum[tid] : 0;     // bid <= 127
#pragma unroll
            for (int d = 16; d >= 1; d >>= 1)
                vp += __shfl_down_sync(0xFFFFFFFFu, vp, d);
            if ((tid & 31) == 0) s_part[tid >> 5] = vp;
        }
        __syncthreads();
        if (tid == 0)
            s_pref = s_part[0] + s_part[1] + s_part[2] + s_part[3];
        __syncthreads();

        int i = bid * TB + tid;
        if (i < N) {
            int o = g_off[i] + s_pref;
            g_off[i] = o;
            g_pos[i] = o;
        }
    }
    if (bid == 0 && tid == 0) g_off[N] = E;

    grid_barrier();

    // ---- Phase 4: bin edges into CSR order --------------------------------
    for (int e = gtid; e < E; e += stride) {
        int r = __ldg(row + e);
        int p = atomicAdd(&g_pos[r], 1);
        g_edge[p] = make_int2(__ldg(col + e), __float_as_int(__ldg(vals + e)));
    }
}

// ---------------------------------------------------------------------------
// Branch B) Y = X @ W^T  (register-tiled GEMM, 64x64 tile, 4x4 micro-tile)
// Runs concurrently with csr_build on a forked stream.
// ---------------------------------------------------------------------------
#define TPAD 68   // row stride in floats (272B, 16B-aligned)

__global__ __launch_bounds__(256) void xform_kernel(
    const float* __restrict__ X,      // [N, 64]
    const float* __restrict__ W,      // [64, 64]
    int N)
{
    __shared__ float Xs[D * TPAD];   // Xs[k][m]
    __shared__ float Ws[D * TPAD];   // Ws[k][o]

    const int tid = threadIdx.x;
    const int node0 = blockIdx.x * 64;

    {
        int r  = tid >> 4;
        int cv = tid & 15;
#pragma unroll
        for (int p = 0; p < 4; p++) {
            int rowi = r + p * 16;
            float4 w = *(const float4*)(W + rowi * D + cv * 4);
            Ws[(cv * 4 + 0) * TPAD + rowi] = w.x;
            Ws[(cv * 4 + 1) * TPAD + rowi] = w.y;
            Ws[(cv * 4 + 2) * TPAD + rowi] = w.z;
            Ws[(cv * 4 + 3) * TPAD + rowi] = w.w;
            int n = node0 + rowi;
            float4 x = (n < N) ? *(const float4*)(X + (size_t)n * D + cv * 4)
                               : make_float4(0.f, 0.f, 0.f, 0.f);
            Xs[(cv * 4 + 0) * TPAD + rowi] = x.x;
            Xs[(cv * 4 + 1) * TPAD + rowi] = x.y;
            Xs[(cv * 4 + 2) * TPAD + rowi] = x.z;
            Xs[(cv * 4 + 3) * TPAD + rowi] = x.w;
        }
    }
    __syncthreads();

    const int tx = tid & 15;
    const int ty = tid >> 4;
    const int m4 = ty * 4;
    const int n4 = tx * 4;

    float acc[4][4];
#pragma unroll
    for (int i = 0; i < 4; i++)
#pragma unroll
        for (int j = 0; j < 4; j++) acc[i][j] = 0.f;

#pragma unroll 8
    for (int k = 0; k < D; k++) {
        float4 xf = *(const float4*)(Xs + k * TPAD + m4);
        float4 wf = *(const float4*)(Ws + k * TPAD + n4);
        const float xv[4] = {xf.x, xf.y, xf.z, xf.w};
        const float wv[4] = {wf.x, wf.y, wf.z, wf.w};
#pragma unroll
        for (int i = 0; i < 4; i++)
#pragma unroll
            for (int j = 0; j < 4; j++)
                acc[i][j] += xv[i] * wv[j];
    }

#pragma unroll
    for (int i = 0; i < 4; i++) {
        int n = node0 + m4 + i;
        if (n < N)
            g_Y[(size_t)n * DV + tx] =
                make_float4(acc[i][0], acc[i][1], acc[i][2], acc[i][3]);
    }
}

// ---------------------------------------------------------------------------
// Join) gather: out[n] = bias + sum over in-edges of val * Y[col]
//       16 lanes per node, lane q owns float4 chunk q. Unroll 8/4 for MLP.
// ---------------------------------------------------------------------------
__global__ __launch_bounds__(256) void gather_bias_kernel(
    const float4* __restrict__ bias,   // [16]
    float4*       __restrict__ out,    // [N*16]
    int N)
{
    int t = blockIdx.x * 256 + threadIdx.x;
    int n = t >> 4;
    int q = t & 15;
    if (n >= N) return;

    int s = __ldg(&g_off[n]);
    int e = __ldg(&g_off[n + 1]);

    float4 acc = __ldg(bias + q);
    int j = s;

    for (; j + 8 <= e; j += 8) {
        int2 p[8];
#pragma unroll
        for (int u = 0; u < 8; u++) p[u] = g_edge[j + u];
        float4 x[8];
#pragma unroll
        for (int u = 0; u < 8; u++)
            x[u] = __ldg(&g_Y[(size_t)p[u].x * DV + q]);
#pragma unroll
        for (int u = 0; u < 8; u++) {
            float v = __int_as_float(p[u].y);
            acc.x += v * x[u].x; acc.y += v * x[u].y;
            acc.z += v * x[u].z; acc.w += v * x[u].w;
        }
    }
    for (; j + 4 <= e; j += 4) {
        int2 p[4];
#pragma unroll
        for (int u = 0; u < 4; u++) p[u] = g_edge[j + u];
        float4 x[4];
#pragma unroll
        for (int u = 0; u < 4; u++)
            x[u] = __ldg(&g_Y[(size_t)p[u].x * DV + q]);
#pragma unroll
        for (int u = 0; u < 4; u++) {
            float v = __int_as_float(p[u].y);
            acc.x += v * x[u].x; acc.y += v * x[u].y;
            acc.z += v * x[u].z; acc.w += v * x[u].w;
        }
    }
    for (; j < e; j++) {
        int2 p = g_edge[j];
        float4 x = __ldg(&g_Y[(size_t)p.x * DV + q]);
        float v = __int_as_float(p.y);
        acc.x += v * x.x; acc.y += v * x.y; acc.z += v * x.z; acc.w += v * x.w;
    }
    out[(size_t)n * DV + q] = acc;
}

// ---------------------------------------------------------------------------
// Launch: inputs in metadata order: row, col, vals, X, weight, bias
// Fork/join via event pattern -> parallel graph branches. Stream/events are
// created per call and intentionally not destroyed (few calls total;
// destroying capture-participating resources mid-capture is illegal).
// ---------------------------------------------------------------------------
extern "C" void kernel_launch(void* const* d_in, const int* in_sizes, int n_in,
                              void* d_out, int out_size)
{
    const int*   row  = (const int*)  d_in[0];
    const int*   col  = (const int*)  d_in[1];
    const float* vals = (const float*)d_in[2];
    const float* X    = (const float*)d_in[3];
    const float* W    = (const float*)d_in[4];
    const float* bias = (const float*)d_in[5];
    float*       out  = (float*)d_out;

    int E = in_sizes[0];
    int N = in_sizes[3] / D;   // 100000

    cudaStream_t s2;
    cudaEvent_t evFork, evJoin;
    cudaStreamCreateWithFlags(&s2, cudaStreamNonBlocking);
    cudaEventCreateWithFlags(&evFork, cudaEventDisableTiming);
    cudaEventCreateWithFlags(&evJoin, cudaEventDisableTiming);

    // Fork: GEMM branch on s2 (co-resides with mem-bound CSR phases)
    cudaEventRecord(evFork, 0);
    cudaStreamWaitEvent(s2, evFork, 0);
    xform_kernel<<<(N + 63) / 64, 256, 0, s2>>>(X, W, N);

    // CSR build: single fused persistent kernel on the capturing stream
    csr_build_kernel<<<NB, TB>>>(row, col, vals, E, N);

    // Join
    cudaEventRecord(evJoin, s2);
    cudaStreamWaitEvent(0, evJoin, 0);

    int threads_gather = N * DV;                       // 16 lanes per node
    gather_bias_kernel<<<(threads_gather + 255) / 256, 256>>>(
        (const float4*)bias, (float4*)out, N);
}

// round 10
// speedup vs baseline: 1.0752x; 1.0752x over previous
#include <cuda_runtime.h>

#define D       64
#define DV      16          // D/4 float4 per row
#define MAX_N   100000
#define MAX_E   1700000
#define NBLK    128         // prep grid: <= SM count -> fully resident
#define TB      1024
#define HALF    512

// ---------------------------------------------------------------------------
// Device-global scratch (no allocation allowed).
// g_cnt is zero at load and restored to zero every execution (read-and-clear).
// Barrier gen/cnt are self-restoring across graph replays.
// ---------------------------------------------------------------------------
__device__ int    g_cnt[MAX_N];        // histogram of destination rows
__device__ int    g_off[MAX_N + 1];    // exclusive CSR offsets
__device__ int    g_pos[MAX_N];        // working cursor for binning
__device__ int    g_bsum[NBLK];        // per-chunk scan totals
__device__ int2   g_edge[MAX_E];       // binned (col, val-bits) pairs
__device__ float4 g_Y[MAX_N * DV];     // Y = X @ W^T

__device__ volatile unsigned g_bar_gen;
__device__ unsigned          g_bar_cnt;

// Named barriers: id 1 = GEMM half (512 thr), id 2 = CSR half (512 thr).
#define GEMM_BAR() asm volatile("bar.sync 1, 512;" ::: "memory")
#define CSR_BAR()  asm volatile("bar.sync 2, 512;" ::: "memory")

// Grid barrier among the 128 CSR halves only (lead thread = tid HALF).
__device__ __forceinline__ void csr_grid_barrier(int ct) {
    CSR_BAR();
    if (ct == 0) {
        unsigned gen = g_bar_gen;
        __threadfence();
        unsigned my = atomicAdd(&g_bar_cnt, 1u);
        if (my == NBLK - 1) {
            g_bar_cnt = 0;
            __threadfence();
            g_bar_gen = gen + 1;
        } else {
            while (g_bar_gen == gen) { }
            __threadfence();
        }
    }
    CSR_BAR();
}

// ---------------------------------------------------------------------------
// prep_kernel: split-block specialization.
//   warps 0..15  : Y = X @ W^T (128x64 tiles, 4x4 micro-tile, FMA-bound)
//   warps 16..31 : CSR build (hist -> scan -> prefix -> bin, LSU/L2-bound)
// Dynamic smem: Xs[128*64] + Ws[64*68] floats = 50176 B (GEMM half only).
// ---------------------------------------------------------------------------
__global__ __launch_bounds__(TB, 1) void prep_kernel(
    const int*   __restrict__ row,
    const int*   __restrict__ col,
    const float* __restrict__ vals,
    const float4* __restrict__ X4,    // [N*16]
    const float4* __restrict__ W4,    // [64*16]
    int E, int N)
{
    extern __shared__ float smem[];
    float* Xs = smem;                 // [128][64]  natural (m-major)
    float* Ws = smem + 128 * 64;      // [64][68]   k-major (transposed)

    __shared__ int s_warp[16];        // CSR: warp scan sums
    __shared__ int s_part[4];         // CSR: prefix reduce partials
    __shared__ int s_pref;            // CSR: chunk prefix

    const int tid = threadIdx.x;
    const int bid = blockIdx.x;

    if (tid < HALF) {
        // ================= GEMM half =================
        const int t0 = tid;

        // Stage W transposed once (8-way STS conflict, 16KB, amortized)
        for (int i = t0; i < 64 * 16; i += HALF) {
            int r  = i >> 4;
            int cv = i & 15;
            float4 w = __ldg(W4 + i);
            Ws[(cv * 4 + 0) * 68 + r] = w.x;
            Ws[(cv * 4 + 1) * 68 + r] = w.y;
            Ws[(cv * 4 + 2) * 68 + r] = w.z;
            Ws[(cv * 4 + 3) * 68 + r] = w.w;
        }
        GEMM_BAR();

        const int ty = t0 >> 4;       // 0..31 -> m rows ty*4..+3
        const int tx = t0 & 15;       // out group tx*4..+3
        const int m4 = ty * 4;
        const int n4 = tx * 4;
        const int T  = (N + 127) >> 7;  // 782 tiles of 128 nodes

        for (int t = bid; t < T; t += NBLK) {
            const int node0 = t << 7;

            // Stage X tile, natural layout (coalesced, conflict-free)
            for (int i = t0; i < 128 * 16; i += HALF) {
                int rrow = i >> 4;
                int cv   = i & 15;
                int n = node0 + rrow;
                float4 x = (n < N) ? __ldg(X4 + (size_t)n * 16 + cv)
                                   : make_float4(0.f, 0.f, 0.f, 0.f);
                *(float4*)(Xs + rrow * 64 + cv * 4) = x;
            }
            GEMM_BAR();

            float acc[4][4];
#pragma unroll
            for (int i = 0; i < 4; i++)
#pragma unroll
                for (int j = 0; j < 4; j++) acc[i][j] = 0.f;

#pragma unroll 4
            for (int k4 = 0; k4 < 16; k4++) {
                float4 xv[4];
#pragma unroll
                for (int i = 0; i < 4; i++)
                    xv[i] = *(const float4*)(Xs + (m4 + i) * 64 + k4 * 4);
#pragma unroll
                for (int kk = 0; kk < 4; kk++) {
                    float4 wv = *(const float4*)(Ws + (k4 * 4 + kk) * 68 + n4);
#pragma unroll
                    for (int i = 0; i < 4; i++) {
                        float xc = ((const float*)&xv[i])[kk];
                        acc[i][0] += xc * wv.x;
                        acc[i][1] += xc * wv.y;
                        acc[i][2] += xc * wv.z;
                        acc[i][3] += xc * wv.w;
                    }
                }
            }

#pragma unroll
            for (int i = 0; i < 4; i++) {
                int n = node0 + m4 + i;
                if (n < N)
                    g_Y[(size_t)n * DV + tx] =
                        make_float4(acc[i][0], acc[i][1], acc[i][2], acc[i][3]);
            }
            GEMM_BAR();   // before next tile's Xs restage
        }
    } else {
        // ================= CSR half =================
        const int ct      = tid - HALF;           // 0..511
        const int gct     = bid * HALF + ct;      // 0..65535
        const int cstride = NBLK * HALF;          // 65536

        // ---- Phase 1: histogram (batch 4 for MLP) ----
        {
            int e = gct;
            for (; e + 3 * cstride < E; e += 4 * cstride) {
                int r0 = __ldg(row + e);
                int r1 = __ldg(row + e + cstride);
                int r2 = __ldg(row + e + 2 * cstride);
                int r3 = __ldg(row + e + 3 * cstride);
                atomicAdd(&g_cnt[r0], 1);
                atomicAdd(&g_cnt[r1], 1);
                atomicAdd(&g_cnt[r2], 1);
                atomicAdd(&g_cnt[r3], 1);
            }
            for (; e < E; e += cstride)
                atomicAdd(&g_cnt[__ldg(row + e)], 1);
        }
        csr_grid_barrier(ct);

        // ---- Phase 2: per-chunk exclusive scan (chunk = 1024, 2 elems/thr) ----
        const int nch = (N + TB - 1) / TB;        // 98
        if (bid < nch) {
            int base = bid * TB + ct * 2;
            int a = 0, b = 0;
            if (base < N)     { a = g_cnt[base];     g_cnt[base]     = 0; }
            if (base + 1 < N) { b = g_cnt[base + 1]; g_cnt[base + 1] = 0; }
            int v = a + b;

            int lane = ct & 31;
            int w    = ct >> 5;                   // 0..15
            int s = v;
#pragma unroll
            for (int d = 1; d < 32; d <<= 1) {
                int t = __shfl_up_sync(0xFFFFFFFFu, s, d);
                if (lane >= d) s += t;
            }
            if (lane == 31) s_warp[w] = s;
            CSR_BAR();
            if (w == 0) {
                int ws = (lane < 16) ? s_warp[lane] : 0;
#pragma unroll
                for (int d = 1; d < 16; d <<= 1) {
                    int t = __shfl_up_sync(0xFFFFFFFFu, ws, d);
                    if (lane >= d) ws += t;
                }
                if (lane < 16) s_warp[lane] = ws;
            }
            CSR_BAR();
            int excl = s - v + (w ? s_warp[w - 1] : 0);
            if (base < N)     g_off[base]     = excl;
            if (base + 1 < N) g_off[base + 1] = excl + a;
            if (ct == HALF - 1) g_bsum[bid] = excl + v;   // chunk total
        }
        csr_grid_barrier(ct);

        // ---- Phase 3: add chunk prefix, init cursors ----
        if (bid < nch) {
            if (ct < 128) {
                int vp = (ct < bid) ? g_bsum[ct] : 0;     // bid <= 97
#pragma unroll
                for (int d = 16; d >= 1; d >>= 1)
                    vp += __shfl_down_sync(0xFFFFFFFFu, vp, d);
                if ((ct & 31) == 0) s_part[ct >> 5] = vp;
            }
            CSR_BAR();
            if (ct == 0)
                s_pref = s_part[0] + s_part[1] + s_part[2] + s_part[3];
            CSR_BAR();
            int pref = s_pref;
            int base = bid * TB + ct * 2;
            if (base < N) {
                int o = g_off[base] + pref;
                g_off[base] = o; g_pos[base] = o;
            }
            if (base + 1 < N) {
                int o = g_off[base + 1] + pref;
                g_off[base + 1] = o; g_pos[base + 1] = o;
            }
        }
        if (bid == 0 && ct == 0) g_off[N] = E;
        csr_grid_barrier(ct);

        // ---- Phase 4: bin edges (batch 4 for MLP) ----
        {
            int e = gct;
            for (; e + 3 * cstride < E; e += 4 * cstride) {
                int e1 = e + cstride, e2 = e + 2 * cstride, e3 = e + 3 * cstride;
                int   r0 = __ldg(row + e),  r1 = __ldg(row + e1);
                int   r2 = __ldg(row + e2), r3 = __ldg(row + e3);
                int   c0 = __ldg(col + e),  c1 = __ldg(col + e1);
                int   c2 = __ldg(col + e2), c3 = __ldg(col + e3);
                float v0 = __ldg(vals + e),  v1 = __ldg(vals + e1);
                float v2 = __ldg(vals + e2), v3 = __ldg(vals + e3);
                int p0 = atomicAdd(&g_pos[r0], 1);
                int p1 = atomicAdd(&g_pos[r1], 1);
                int p2 = atomicAdd(&g_pos[r2], 1);
                int p3 = atomicAdd(&g_pos[r3], 1);
                g_edge[p0] = make_int2(c0, __float_as_int(v0));
                g_edge[p1] = make_int2(c1, __float_as_int(v1));
                g_edge[p2] = make_int2(c2, __float_as_int(v2));
                g_edge[p3] = make_int2(c3, __float_as_int(v3));
            }
            for (; e < E; e += cstride) {
                int r = __ldg(row + e);
                int p = atomicAdd(&g_pos[r], 1);
                g_edge[p] = make_int2(__ldg(col + e),
                                      __float_as_int(__ldg(vals + e)));
            }
        }
    }
}

// ---------------------------------------------------------------------------
// gather: out[n] = bias + sum over in-edges of val * Y[col]
// 16 lanes per node, lane q owns float4 chunk q. Unroll 8/4 for MLP. (Proven.)
// ---------------------------------------------------------------------------
__global__ __launch_bounds__(256) void gather_bias_kernel(
    const float4* __restrict__ bias,   // [16]
    float4*       __restrict__ out,    // [N*16]
    int N)
{
    int t = blockIdx.x * 256 + threadIdx.x;
    int n = t >> 4;
    int q = t & 15;
    if (n >= N) return;

    int s = __ldg(&g_off[n]);
    int e = __ldg(&g_off[n + 1]);

    float4 acc = __ldg(bias + q);
    int j = s;

    for (; j + 8 <= e; j += 8) {
        int2 p[8];
#pragma unroll
        for (int u = 0; u < 8; u++) p[u] = g_edge[j + u];
        float4 x[8];
#pragma unroll
        for (int u = 0; u < 8; u++)
            x[u] = __ldg(&g_Y[(size_t)p[u].x * DV + q]);
#pragma unroll
        for (int u = 0; u < 8; u++) {
            float v = __int_as_float(p[u].y);
            acc.x += v * x[u].x; acc.y += v * x[u].y;
            acc.z += v * x[u].z; acc.w += v * x[u].w;
        }
    }
    for (; j + 4 <= e; j += 4) {
        int2 p[4];
#pragma unroll
        for (int u = 0; u < 4; u++) p[u] = g_edge[j + u];
        float4 x[4];
#pragma unroll
        for (int u = 0; u < 4; u++)
            x[u] = __ldg(&g_Y[(size_t)p[u].x * DV + q]);
#pragma unroll
        for (int u = 0; u < 4; u++) {
            float v = __int_as_float(p[u].y);
            acc.x += v * x[u].x; acc.y += v * x[u].y;
            acc.z += v * x[u].z; acc.w += v * x[u].w;
        }
    }
    for (; j < e; j++) {
        int2 p = g_edge[j];
        float4 x = __ldg(&g_Y[(size_t)p.x * DV + q]);
        float v = __int_as_float(p.y);
        acc.x += v * x.x; acc.y += v * x.y; acc.z += v * x.z; acc.w += v * x.w;
    }
    out[(size_t)n * DV + q] = acc;
}

// ---------------------------------------------------------------------------
// Launch: inputs in metadata order: row, col, vals, X, weight, bias
// Two graph nodes total: prep (GEMM || CSR fused, grid-resident) -> gather.
// ---------------------------------------------------------------------------
extern "C" void kernel_launch(void* const* d_in, const int* in_sizes, int n_in,
                              void* d_out, int out_size)
{
    const int*   row  = (const int*)  d_in[0];
    const int*   col  = (const int*)  d_in[1];
    const float* vals = (const float*)d_in[2];
    const float* X    = (const float*)d_in[3];
    const float* W    = (const float*)d_in[4];
    const float* bias = (const float*)d_in[5];
    float*       out  = (float*)d_out;

    int E = in_sizes[0];
    int N = in_sizes[3] / D;   // 100000

    const int smem_bytes = (128 * 64 + 64 * 68) * 4;   // 50176
    static bool attr_set = false;
    if (!attr_set) {
        cudaFuncSetAttribute(prep_kernel,
                             cudaFuncAttributeMaxDynamicSharedMemorySize,
                             smem_bytes);
        attr_set = true;
    }

    prep_kernel<<<NBLK, TB, smem_bytes>>>(
        row, col, vals, (const float4*)X, (const float4*)W, E, N);

    int threads_gather = N * DV;                       // 16 lanes per node
    gather_bias_kernel<<<(threads_gather + 255) / 256, 256>>>(
        (const float4*)bias, (float4*)out, N);
}

// round 11
// speedup vs baseline: 1.0907x; 1.0144x over previous
#include <cuda_runtime.h>
#include <cuda_fp16.h>

#define D       64
#define DV      16          // float4 chunks per row (fp32) / uint2 chunks (fp16)
#define MAX_N   100000
#define MAX_E   1700000
#define NB      128         // persistent grid: <= SM count -> all resident
#define TB      1024

// ---------------------------------------------------------------------------
// Device-global scratch (no allocation allowed).
// g_cnt is zero at load and restored to zero each execution (read-and-clear).
// Barrier gen/cnt are self-restoring across graph replays.
// ---------------------------------------------------------------------------
__device__ int    g_cnt[MAX_N];        // histogram of destination rows
__device__ int    g_off[MAX_N + 1];    // exclusive CSR offsets
__device__ int    g_pos[MAX_N];        // working cursor for binning
__device__ int    g_bsum[NB];          // per-chunk scan totals
__device__ int2   g_edge[MAX_E];       // binned (col, val-bits) pairs
__device__ uint2  g_Yh[MAX_N * DV];    // Y = X @ W^T in fp16 (4 halves per uint2)

__device__ volatile unsigned g_bar_gen;
__device__ unsigned          g_bar_cnt;

// Sense-reversing software grid barrier (grid fully resident: NB=128 <= SMs).
__device__ __forceinline__ void grid_barrier() {
    __syncthreads();
    if (threadIdx.x == 0) {
        unsigned gen = g_bar_gen;
        __threadfence();
        unsigned my = atomicAdd(&g_bar_cnt, 1u);
        if (my == gridDim.x - 1) {
            g_bar_cnt = 0;
            __threadfence();
            g_bar_gen = gen + 1;
        } else {
            while (g_bar_gen == gen) { }
            __threadfence();
        }
    }
    __syncthreads();
}

// ---------------------------------------------------------------------------
// Fused CSR build: hist -> chunk scan -> prefix apply -> bin, one kernel.
// (Identical to the 109.3us-proven R8 version.)
// ---------------------------------------------------------------------------
__global__ __launch_bounds__(TB, 2) void csr_build_kernel(
    const int* __restrict__ row, const int* __restrict__ col,
    const float* __restrict__ vals, int E, int N)
{
    const int tid    = threadIdx.x;
    const int bid    = blockIdx.x;
    const int gtid   = bid * TB + tid;
    const int stride = NB * TB;            // 131072
    const int nch    = (N + TB - 1) / TB;  // 98 chunks of 1024

    // ---- Phase 1: histogram of row[] --------------------------------------
    for (int e = gtid; e < E; e += stride)
        atomicAdd(&g_cnt[__ldg(row + e)], 1);

    grid_barrier();

    // ---- Phase 2: per-chunk exclusive scan (block b scans chunk b) --------
    __shared__ int wsum[32];
    if (bid < nch) {
        int i = bid * TB + tid;
        int v = 0;
        if (i < N) { v = g_cnt[i]; g_cnt[i] = 0; }   // read + restore invariant

        int lane = tid & 31;
        int wid  = tid >> 5;

        int s = v;
#pragma unroll
        for (int d = 1; d < 32; d <<= 1) {
            int t = __shfl_up_sync(0xFFFFFFFFu, s, d);
            if (lane >= d) s += t;
        }
        if (lane == 31) wsum[wid] = s;
        __syncthreads();
        if (wid == 0) {
            int ws = wsum[lane];
#pragma unroll
            for (int d = 1; d < 32; d <<= 1) {
                int t = __shfl_up_sync(0xFFFFFFFFu, ws, d);
                if (lane >= d) ws += t;
            }
            wsum[lane] = ws;
        }
        __syncthreads();
        int incl = s + (wid == 0 ? 0 : wsum[wid - 1]);
        if (i < N) g_off[i] = incl - v;                 // chunk-local exclusive
        if (tid == TB - 1) g_bsum[bid] = incl;          // chunk total
    }

    grid_barrier();

    // ---- Phase 3: add chunk prefix, write final g_off, init g_pos ---------
    __shared__ int s_part[4];
    __shared__ int s_pref;
    if (bid < nch) {
        if (tid < 128) {
            int vp = (tid < bid) ? g_bsum[tid] : 0;     // bid <= 127
#pragma unroll
            for (int d = 16; d >= 1; d >>= 1)
                vp += __shfl_down_sync(0xFFFFFFFFu, vp, d);
            if ((tid & 31) == 0) s_part[tid >> 5] = vp;
        }
        __syncthreads();
        if (tid == 0)
            s_pref = s_part[0] + s_part[1] + s_part[2] + s_part[3];
        __syncthreads();

        int i = bid * TB + tid;
        if (i < N) {
            int o = g_off[i] + s_pref;
            g_off[i] = o;
            g_pos[i] = o;
        }
    }
    if (bid == 0 && tid == 0) g_off[N] = E;

    grid_barrier();

    // ---- Phase 4: bin edges into CSR order --------------------------------
    for (int e = gtid; e < E; e += stride) {
        int r = __ldg(row + e);
        int p = atomicAdd(&g_pos[r], 1);
        g_edge[p] = make_int2(__ldg(col + e), __float_as_int(__ldg(vals + e)));
    }
}

// ---------------------------------------------------------------------------
// Branch B) Y = X @ W^T, stored fp16 (half2 pairs). Register-tiled GEMM,
// 64x64 tile, 4x4 micro-tile. Runs concurrently with csr_build (forked).
// ---------------------------------------------------------------------------
#define TPAD 68   // row stride in floats (272B, 16B-aligned)

__global__ __launch_bounds__(256) void xform_kernel(
    const float* __restrict__ X,      // [N, 64]
    const float* __restrict__ W,      // [64, 64]
    int N)
{
    __shared__ float Xs[D * TPAD];   // Xs[k][m]
    __shared__ float Ws[D * TPAD];   // Ws[k][o]

    const int tid = threadIdx.x;
    const int node0 = blockIdx.x * 64;

    {
        int r  = tid >> 4;
        int cv = tid & 15;
#pragma unroll
        for (int p = 0; p < 4; p++) {
            int rowi = r + p * 16;
            float4 w = *(const float4*)(W + rowi * D + cv * 4);
            Ws[(cv * 4 + 0) * TPAD + rowi] = w.x;
            Ws[(cv * 4 + 1) * TPAD + rowi] = w.y;
            Ws[(cv * 4 + 2) * TPAD + rowi] = w.z;
            Ws[(cv * 4 + 3) * TPAD + rowi] = w.w;
            int n = node0 + rowi;
            float4 x = (n < N) ? *(const float4*)(X + (size_t)n * D + cv * 4)
                               : make_float4(0.f, 0.f, 0.f, 0.f);
            Xs[(cv * 4 + 0) * TPAD + rowi] = x.x;
            Xs[(cv * 4 + 1) * TPAD + rowi] = x.y;
            Xs[(cv * 4 + 2) * TPAD + rowi] = x.z;
            Xs[(cv * 4 + 3) * TPAD + rowi] = x.w;
        }
    }
    __syncthreads();

    const int tx = tid & 15;
    const int ty = tid >> 4;
    const int m4 = ty * 4;
    const int n4 = tx * 4;

    float acc[4][4];
#pragma unroll
    for (int i = 0; i < 4; i++)
#pragma unroll
        for (int j = 0; j < 4; j++) acc[i][j] = 0.f;

#pragma unroll 8
    for (int k = 0; k < D; k++) {
        float4 xf = *(const float4*)(Xs + k * TPAD + m4);
        float4 wf = *(const float4*)(Ws + k * TPAD + n4);
        const float xv[4] = {xf.x, xf.y, xf.z, xf.w};
        const float wv[4] = {wf.x, wf.y, wf.z, wf.w};
#pragma unroll
        for (int i = 0; i < 4; i++)
#pragma unroll
            for (int j = 0; j < 4; j++)
                acc[i][j] += xv[i] * wv[j];
    }

#pragma unroll
    for (int i = 0; i < 4; i++) {
        int n = node0 + m4 + i;
        if (n < N) {
            __half2 h01 = __floats2half2_rn(acc[i][0], acc[i][1]);
            __half2 h23 = __floats2half2_rn(acc[i][2], acc[i][3]);
            uint2 u;
            u.x = *reinterpret_cast<unsigned*>(&h01);
            u.y = *reinterpret_cast<unsigned*>(&h23);
            g_Yh[(size_t)n * DV + tx] = u;
        }
    }
}

// ---------------------------------------------------------------------------
// Join) gather: out[n] = bias + sum over in-edges of val * Yh[col]
// 16 lanes per node; lane q owns uint2 chunk q (4 halves -> 4 output floats).
// fp32 accumulation. Unroll 8/4 for MLP.
// ---------------------------------------------------------------------------
__device__ __forceinline__ void fma_h4(float4& acc, float v, uint2 y) {
    __half2 h01 = *reinterpret_cast<__half2*>(&y.x);
    __half2 h23 = *reinterpret_cast<__half2*>(&y.y);
    float2 f01 = __half22float2(h01);
    float2 f23 = __half22float2(h23);
    acc.x += v * f01.x; acc.y += v * f01.y;
    acc.z += v * f23.x; acc.w += v * f23.y;
}

__global__ __launch_bounds__(256) void gather_bias_kernel(
    const float4* __restrict__ bias,   // [16]
    float4*       __restrict__ out,    // [N*16]
    int N)
{
    int t = blockIdx.x * 256 + threadIdx.x;
    int n = t >> 4;
    int q = t & 15;
    if (n >= N) return;

    int s = __ldg(&g_off[n]);
    int e = __ldg(&g_off[n + 1]);

    float4 acc = __ldg(bias + q);
    int j = s;

    for (; j + 8 <= e; j += 8) {
        int2 p[8];
#pragma unroll
        for (int u = 0; u < 8; u++) p[u] = g_edge[j + u];
        uint2 y[8];
#pragma unroll
        for (int u = 0; u < 8; u++)
            y[u] = __ldg(&g_Yh[(size_t)p[u].x * DV + q]);
#pragma unroll
        for (int u = 0; u < 8; u++)
            fma_h4(acc, __int_as_float(p[u].y), y[u]);
    }
    for (; j + 4 <= e; j += 4) {
        int2 p[4];
#pragma unroll
        for (int u = 0; u < 4; u++) p[u] = g_edge[j + u];
        uint2 y[4];
#pragma unroll
        for (int u = 0; u < 4; u++)
            y[u] = __ldg(&g_Yh[(size_t)p[u].x * DV + q]);
#pragma unroll
        for (int u = 0; u < 4; u++)
            fma_h4(acc, __int_as_float(p[u].y), y[u]);
    }
    for (; j < e; j++) {
        int2 p = g_edge[j];
        uint2 y = __ldg(&g_Yh[(size_t)p.x * DV + q]);
        fma_h4(acc, __int_as_float(p.y), y);
    }
    out[(size_t)n * DV + q] = acc;
}

// ---------------------------------------------------------------------------
// Launch: inputs in metadata order: row, col, vals, X, weight, bias
// Fork/join via event pattern -> parallel graph branches (R8-proven).
// Stream/events created per call, intentionally not destroyed (few calls;
// destroying capture-participating resources mid-capture is illegal).
// ---------------------------------------------------------------------------
extern "C" void kernel_launch(void* const* d_in, const int* in_sizes, int n_in,
                              void* d_out, int out_size)
{
    const int*   row  = (const int*)  d_in[0];
    const int*   col  = (const int*)  d_in[1];
    const float* vals = (const float*)d_in[2];
    const float* X    = (const float*)d_in[3];
    const float* W    = (const float*)d_in[4];
    const float* bias = (const float*)d_in[5];
    float*       out  = (float*)d_out;

    int E = in_sizes[0];
    int N = in_sizes[3] / D;   // 100000

    cudaStream_t s2;
    cudaEvent_t evFork, evJoin;
    cudaStreamCreateWithFlags(&s2, cudaStreamNonBlocking);
    cudaEventCreateWithFlags(&evFork, cudaEventDisableTiming);
    cudaEventCreateWithFlags(&evJoin, cudaEventDisableTiming);

    // Fork: GEMM branch on s2
    cudaEventRecord(evFork, 0);
    cudaStreamWaitEvent(s2, evFork, 0);
    xform_kernel<<<(N + 63) / 64, 256, 0, s2>>>(X, W, N);

    // CSR build: single fused persistent kernel on the capturing stream
    csr_build_kernel<<<NB, TB>>>(row, col, vals, E, N);

    // Join
    cudaEventRecord(evJoin, s2);
    cudaStreamWaitEvent(0, evJoin, 0);

    int threads_gather = N * DV;                       // 16 lanes per node
    gather_bias_kernel<<<(threads_gather + 255) / 256, 256>>>(
        (const float4*)bias, (float4*)out, N);
}

// round 14
// speedup vs baseline: 1.3351x; 1.2241x over previous
#include <cuda_runtime.h>
#include <cuda_fp16.h>

#define D       64
#define DV      16          // uint2 (4-half) chunks per row
#define MAX_N   100000
#define MAX_E   1700000
#define NB      128         // persistent grid: <= SM count -> all resident
#define TB      1024
#define XS      72          // smem row stride in halves (bank-conflict-free)

// ---------------------------------------------------------------------------
// Device-global scratch (no allocation allowed).
// g_cnt is zero at load and restored to zero each execution (read-and-clear).
// Barrier gen/cnt are self-restoring across graph replays.
// ---------------------------------------------------------------------------
__device__ int    g_cnt[MAX_N];        // histogram of destination rows
__device__ int    g_off[MAX_N + 1];    // exclusive CSR offsets
__device__ int    g_pos[MAX_N];        // working cursor for binning
__device__ int    g_bsum[NB];          // per-chunk scan totals
__device__ int2   g_edge[MAX_E];       // binned (col, val-bits) pairs
__device__ uint2  g_Yh[MAX_N * DV];    // Y = X @ W^T in fp16

__device__ volatile unsigned g_bar_gen;
__device__ unsigned          g_bar_cnt;

__device__ __forceinline__ void grid_barrier() {
    __syncthreads();
    if (threadIdx.x == 0) {
        unsigned gen = g_bar_gen;
        __threadfence();
        unsigned my = atomicAdd(&g_bar_cnt, 1u);
        if (my == gridDim.x - 1) {
            g_bar_cnt = 0;
            __threadfence();
            g_bar_gen = gen + 1;
        } else {
            while (g_bar_gen == gen) { }
            __threadfence();
        }
    }
    __syncthreads();
}

// ---------------------------------------------------------------------------
// Fused CSR build (109.3us-proven R8 version, unchanged).
// ---------------------------------------------------------------------------
__global__ __launch_bounds__(TB, 2) void csr_build_kernel(
    const int* __restrict__ row, const int* __restrict__ col,
    const float* __restrict__ vals, int E, int N)
{
    const int tid    = threadIdx.x;
    const int bid    = blockIdx.x;
    const int gtid   = bid * TB + tid;
    const int stride = NB * TB;
    const int nch    = (N + TB - 1) / TB;

    for (int e = gtid; e < E; e += stride)
        atomicAdd(&g_cnt[__ldg(row + e)], 1);

    grid_barrier();

    __shared__ int wsum[32];
    if (bid < nch) {
        int i = bid * TB + tid;
        int v = 0;
        if (i < N) { v = g_cnt[i]; g_cnt[i] = 0; }

        int lane = tid & 31;
        int wid  = tid >> 5;

        int s = v;
#pragma unroll
        for (int d = 1; d < 32; d <<= 1) {
            int t = __shfl_up_sync(0xFFFFFFFFu, s, d);
            if (lane >= d) s += t;
        }
        if (lane == 31) wsum[wid] = s;
        __syncthreads();
        if (wid == 0) {
            int ws = wsum[lane];
#pragma unroll
            for (int d = 1; d < 32; d <<= 1) {
                int t = __shfl_up_sync(0xFFFFFFFFu, ws, d);
                if (lane >= d) ws += t;
            }
            wsum[lane] = ws;
        }
        __syncthreads();
        int incl = s + (wid == 0 ? 0 : wsum[wid - 1]);
        if (i < N) g_off[i] = incl - v;
        if (tid == TB - 1) g_bsum[bid] = incl;
    }

    grid_barrier();

    __shared__ int s_part[4];
    __shared__ int s_pref;
    if (bid < nch) {
        if (tid < 128) {
            int vp = (tid < bid) ? g_bsum[tid] : 0;
#pragma unroll
            for (int d = 16; d >= 1; d >>= 1)
                vp += __shfl_down_sync(0xFFFFFFFFu, vp, d);
            if ((tid & 31) == 0) s_part[tid >> 5] = vp;
        }
        __syncthreads();
        if (tid == 0)
            s_pref = s_part[0] + s_part[1] + s_part[2] + s_part[3];
        __syncthreads();

        int i = bid * TB + tid;
        if (i < N) {
            int o = g_off[i] + s_pref;
            g_off[i] = o;
            g_pos[i] = o;
        }
    }
    if (bid == 0 && tid == 0) g_off[N] = E;

    grid_barrier();

    for (int e = gtid; e < E; e += stride) {
        int r = __ldg(row + e);
        int p = atomicAdd(&g_pos[r], 1);
        g_edge[p] = make_int2(__ldg(col + e), __float_as_int(__ldg(vals + e)));
    }
}

// ---------------------------------------------------------------------------
// xform via tensor cores: Yh = fp16( X @ W^T ).
// Block = 128 threads (4 warps), tile = 64 nodes x 64 outs, K = 64.
// mma.sync.m16n8k16.row.col.f32.f16.f16.f32 with MANUAL fragments:
//   lane g = lane>>2 (0..7), c = (lane&3)*2
//   A: a0={A[g][c..]}, a1={A[g+8][c..]}, a2={A[g][c+8..]}, a3={A[g+8][c+8..]}
//   B (col-major k16xn8) = W natural [n][k]: b0={W[n0+g][c..]}, b1={W[n0+g][c+8..]}
//   D: d0=D[g][c], d1=D[g][c+1], d2=D[g+8][c], d3=D[g+8][c+1]
// Smem rows stride XS=72 halves -> word bank = 4g + c/2 : conflict-free.
// ---------------------------------------------------------------------------
__device__ __forceinline__ void mma16816(
    float& d0, float& d1, float& d2, float& d3,
    unsigned a0, unsigned a1, unsigned a2, unsigned a3,
    unsigned b0, unsigned b1)
{
    asm volatile(
        "mma.sync.aligned.m16n8k16.row.col.f32.f16.f16.f32 "
        "{%0,%1,%2,%3}, {%4,%5,%6,%7}, {%8,%9}, {%0,%1,%2,%3};"
        : "+f"(d0), "+f"(d1), "+f"(d2), "+f"(d3)
        : "r"(a0), "r"(a1), "r"(a2), "r"(a3), "r"(b0), "r"(b1));
}

__global__ __launch_bounds__(128) void xform_hmma_kernel(
    const float4* __restrict__ X4,    // [N*16]
    const float4* __restrict__ W4,    // [64*16]
    int N)
{
    __shared__ __align__(16) __half Xh[64 * XS];
    __shared__ __align__(16) __half Wh[64 * XS];

    const int tid   = threadIdx.x;
    const int node0 = blockIdx.x * 64;

    // Stage W and X tile as fp16 (convert inline)
    for (int i = tid; i < 64 * 16; i += 128) {
        int r  = i >> 4;
        int cv = i & 15;
        float4 w = __ldg(W4 + i);
        *(__half2*)(Wh + r * XS + cv * 4)     = __floats2half2_rn(w.x, w.y);
        *(__half2*)(Wh + r * XS + cv * 4 + 2) = __floats2half2_rn(w.z, w.w);

        int n = node0 + r;
        float4 x = (n < N) ? __ldg(X4 + (size_t)n * 16 + cv)
                           : make_float4(0.f, 0.f, 0.f, 0.f);
        *(__half2*)(Xh + r * XS + cv * 4)     = __floats2half2_rn(x.x, x.y);
        *(__half2*)(Xh + r * XS + cv * 4 + 2) = __floats2half2_rn(x.z, x.w);
    }
    __syncthreads();

    const int warp = tid >> 5;
    const int lane = tid & 31;
    const int g    = lane >> 2;        // 0..7
    const int c    = (lane & 3) * 2;   // 0,2,4,6
    const int m0   = warp * 16;        // warp's 16 node rows

    float acc[8][4];
#pragma unroll
    for (int nt = 0; nt < 8; nt++)
#pragma unroll
        for (int i = 0; i < 4; i++) acc[nt][i] = 0.f;

#pragma unroll
    for (int kt = 0; kt < 4; kt++) {
        const int k0 = kt * 16;
        unsigned a0 = *(const unsigned*)(Xh + (m0 + g)     * XS + k0 + c);
        unsigned a1 = *(const unsigned*)(Xh + (m0 + g + 8) * XS + k0 + c);
        unsigned a2 = *(const unsigned*)(Xh + (m0 + g)     * XS + k0 + c + 8);
        unsigned a3 = *(const unsigned*)(Xh + (m0 + g + 8) * XS + k0 + c + 8);
#pragma unroll
        for (int nt = 0; nt < 8; nt++) {
            unsigned b0 = *(const unsigned*)(Wh + (nt * 8 + g) * XS + k0 + c);
            unsigned b1 = *(const unsigned*)(Wh + (nt * 8 + g) * XS + k0 + c + 8);
            mma16816(acc[nt][0], acc[nt][1], acc[nt][2], acc[nt][3],
                     a0, a1, a2, a3, b0, b1);
        }
    }

    // Store D rows (fp16 half2 per n-tile)
    __half* Yh = (__half*)g_Yh;
    int rA = node0 + m0 + g;
    int rB = rA + 8;
#pragma unroll
    for (int nt = 0; nt < 8; nt++) {
        int colh = nt * 8 + c;
        if (rA < N)
            *(__half2*)(Yh + (size_t)rA * D + colh) =
                __floats2half2_rn(acc[nt][0], acc[nt][1]);
        if (rB < N)
            *(__half2*)(Yh + (size_t)rB * D + colh) =
                __floats2half2_rn(acc[nt][2], acc[nt][3]);
    }
}

// ---------------------------------------------------------------------------
// gather: out[n] = bias + sum over in-edges of val * Yh[col]   (R11-proven)
// ---------------------------------------------------------------------------
__device__ __forceinline__ void fma_h4(float4& acc, float v, uint2 y) {
    __half2 h01 = *reinterpret_cast<__half2*>(&y.x);
    __half2 h23 = *reinterpret_cast<__half2*>(&y.y);
    float2 f01 = __half22float2(h01);
    float2 f23 = __half22float2(h23);
    acc.x += v * f01.x; acc.y += v * f01.y;
    acc.z += v * f23.x; acc.w += v * f23.y;
}

__global__ __launch_bounds__(256) void gather_bias_kernel(
    const float4* __restrict__ bias,   // [16]
    float4*       __restrict__ out,    // [N*16]
    int N)
{
    int t = blockIdx.x * 256 + threadIdx.x;
    int n = t >> 4;
    int q = t & 15;
    if (n >= N) return;

    int s = __ldg(&g_off[n]);
    int e = __ldg(&g_off[n + 1]);

    float4 acc = __ldg(bias + q);
    int j = s;

    for (; j + 8 <= e; j += 8) {
        int2 p[8];
#pragma unroll
        for (int u = 0; u < 8; u++) p[u] = g_edge[j + u];
        uint2 y[8];
#pragma unroll
        for (int u = 0; u < 8; u++)
            y[u] = __ldg(&g_Yh[(size_t)p[u].x * DV + q]);
#pragma unroll
        for (int u = 0; u < 8; u++)
            fma_h4(acc, __int_as_float(p[u].y), y[u]);
    }
    for (; j + 4 <= e; j += 4) {
        int2 p[4];
#pragma unroll
        for (int u = 0; u < 4; u++) p[u] = g_edge[j + u];
        uint2 y[4];
#pragma unroll
        for (int u = 0; u < 4; u++)
            y[u] = __ldg(&g_Yh[(size_t)p[u].x * DV + q]);
#pragma unroll
        for (int u = 0; u < 4; u++)
            fma_h4(acc, __int_as_float(p[u].y), y[u]);
    }
    for (; j < e; j++) {
        int2 p = g_edge[j];
        uint2 y = __ldg(&g_Yh[(size_t)p.x * DV + q]);
        fma_h4(acc, __int_as_float(p.y), y);
    }
    out[(size_t)n * DV + q] = acc;
}

// ---------------------------------------------------------------------------
// Launch: inputs in metadata order: row, col, vals, X, weight, bias
// Fork/join -> parallel graph branches. Stream/events created per call and
// intentionally not destroyed (few calls; destroying capture-participating
// resources mid-capture is illegal).
// ---------------------------------------------------------------------------
extern "C" void kernel_launch(void* const* d_in, const int* in_sizes, int n_in,
                              void* d_out, int out_size)
{
    const int*   row  = (const int*)  d_in[0];
    const int*   col  = (const int*)  d_in[1];
    const float* vals = (const float*)d_in[2];
    const float* X    = (const float*)d_in[3];
    const float* W    = (const float*)d_in[4];
    const float* bias = (const float*)d_in[5];
    float*       out  = (float*)d_out;

    int E = in_sizes[0];
    int N = in_sizes[3] / D;   // 100000

    cudaStream_t s2;
    cudaEvent_t evFork, evJoin;
    cudaStreamCreateWithFlags(&s2, cudaStreamNonBlocking);
    cudaEventCreateWithFlags(&evFork, cudaEventDisableTiming);
    cudaEventCreateWithFlags(&evJoin, cudaEventDisableTiming);

    // Fork: HMMA GEMM branch on s2 (tensor-pipe, LSU-light -> real overlap)
    cudaEventRecord(evFork, 0);
    cudaStreamWaitEvent(s2, evFork, 0);
    xform_hmma_kernel<<<(N + 63) / 64, 128, 0, s2>>>(
        (const float4*)X, (const float4*)W, N);

    // CSR build on the capturing stream
    csr_build_kernel<<<NB, TB>>>(row, col, vals, E, N);

    // Join
    cudaEventRecord(evJoin, s2);
    cudaStreamWaitEvent(0, evJoin, 0);

    int threads_gather = N * DV;
    gather_bias_kernel<<<(threads_gather + 255) / 256, 256>>>(
        (const float4*)bias, (float4*)out, N);
}